// round 4
// baseline (speedup 1.0000x reference)
#include <cuda_runtime.h>
#include <math.h>
#include <stdint.h>

#define B_ 8
#define C_ 256
#define H_ 128
#define W_ 128
#define HW_ 16384
#define HEADS_ 8
#define HD_ 32
#define GSEG 4

// ---------------- scratch (device globals; no allocation allowed) ------------
__device__ float g_bufA[B_ * C_ * HW_];          // q_pre, later pemb+hx
__device__ float g_bufB[B_ * 2 * C_ * HW_];      // kv_pre
__device__ float g_q[B_ * C_ * HW_];
__device__ float g_k[B_ * C_ * HW_];
__device__ float g_v[B_ * C_ * HW_];
__device__ float g_Wq[C_ * C_];
__device__ float g_Wkv[2 * C_ * C_];
__device__ float g_bq[C_];
__device__ float g_bkv[2 * C_];
__device__ float g_rsq[C_];
__device__ float g_rskv[2 * C_];
__device__ float g_ss[2 * B_ * C_];              // sum of squares: z=0 q, z=1 k
__device__ float g_part[B_ * HEADS_ * GSEG * 1024];
__device__ float g_attn[B_ * HEADS_ * 1024];
__device__ float g_M[B_ * C_ * C_];

// ---------------- PTX helpers ------------------------------------------------
__device__ __forceinline__ void mma_tf32(float* c, const unsigned* a, unsigned b0, unsigned b1) {
    asm volatile(
        "mma.sync.aligned.m16n8k8.row.col.f32.tf32.tf32.f32 "
        "{%0,%1,%2,%3}, {%4,%5,%6,%7}, {%8,%9}, {%0,%1,%2,%3};\n"
        : "+f"(c[0]), "+f"(c[1]), "+f"(c[2]), "+f"(c[3])
        : "r"(a[0]), "r"(a[1]), "r"(a[2]), "r"(a[3]), "r"(b0), "r"(b1));
}
__device__ __forceinline__ uint32_t smem_u32(const void* p) {
    return (uint32_t)__cvta_generic_to_shared(p);
}
__device__ __forceinline__ void cp16(uint32_t dst, const void* src) {
    asm volatile("cp.async.cg.shared.global [%0], [%1], 16;\n" :: "r"(dst), "l"(src));
}
__device__ __forceinline__ void cp_commit() { asm volatile("cp.async.commit_group;\n"); }
template <int N>
__device__ __forceinline__ void cp_wait() { asm volatile("cp.async.wait_group %0;\n" ::"n"(N)); }

__device__ __forceinline__ float gelu_tanh(float s) {
    float x3 = s * s * s;
    return 0.5f * s * (1.f + tanhf(0.7978845608028654f * (s + 0.044715f * x3)));
}

// 3x3 row-tap over padded smem row (data at +4, zeros at 0..3 and 132..135)
__device__ __forceinline__ void stencil4(const float* R, int c0, float w0, float w1, float w2,
                                         float4& o) {
    float4 m = *reinterpret_cast<const float4*>(R + 4 + c0);
    float l = R[3 + c0];
    float r = R[8 + c0];
    o.x += w0 * l + w1 * m.x + w2 * m.y;
    o.y += w0 * m.x + w1 * m.y + w2 * m.z;
    o.z += w0 * m.y + w1 * m.z + w2 * m.w;
    o.w += w0 * m.z + w1 * m.w + w2 * r;
}

// ---------------- weight prep: fold LN gamma/beta into conv1x1 ---------------
__global__ void prep_w_kernel(const float* __restrict__ qw, const float* __restrict__ qb,
                              const float* __restrict__ ln1w, const float* __restrict__ ln1b,
                              const float* __restrict__ kvw, const float* __restrict__ kvb,
                              const float* __restrict__ ln2w, const float* __restrict__ ln2b) {
    int r = blockIdx.x;
    int tid = threadIdx.x;
    if (r < 16) g_ss[r * 256 + tid] = 0.f;
    const float *w, *lnw, *lnb;
    float cb;
    float *dW, *dB, *dR;
    if (r < C_) {
        int o = r;
        w = qw + (size_t)o * C_; lnw = ln1w; lnb = ln1b; cb = qb[o];
        dW = g_Wq + (size_t)o * C_; dB = g_bq + o; dR = g_rsq + o;
    } else {
        int o = r - C_;
        w = kvw + (size_t)o * C_; lnw = ln2w; lnb = ln2b; cb = kvb[o];
        dW = g_Wkv + (size_t)o * C_; dB = g_bkv + o; dR = g_rskv + o;
    }
    float wv = w[tid];
    float we = wv * lnw[tid];
    dW[tid] = we;
    __shared__ float sh1[256], sh2[256];
    sh1[tid] = we;
    sh2[tid] = wv * lnb[tid];
    __syncthreads();
    for (int s = 128; s > 0; s >>= 1) {
        if (tid < s) { sh1[tid] += sh1[tid + s]; sh2[tid] += sh2[tid + s]; }
        __syncthreads();
    }
    if (tid == 0) { *dR = sh1[0]; *dB = cb + sh2[0]; }
}

// ================== tensor-core GEMM (tf32 mma, cp.async 3-stage) ============
struct GemmArgs {
    const float* X;      // [b][k][p], k stride HW_
    const float* Wg;     // [o][k], row stride C_
    const float* bias;
    const float* rsum;
    const float* pemb;
    float* Y;
    int O;
    int mode;
    int perBatchW;
};

#define ST_FLOATS 8960   // per stage: A 128*36=4608 + B 32*136=4352

__global__ __launch_bounds__(256, 2) void gemm_tc_kernel(GemmArgs ga) {
    extern __shared__ unsigned sm[];
    __shared__ float s_st[4][128];
    int b = blockIdx.z;
    int pBase = blockIdx.x * 128;
    int oBase = blockIdx.y * 128;
    int tid = threadIdx.x;
    int wid = tid >> 5, lane = tid & 31;
    int g = lane >> 2, tig = lane & 3;
    int oW = (wid >> 2) * 64;
    int pW = (wid & 3) * 32;

    const float* Xb = ga.X + (size_t)b * C_ * HW_;
    const float* Wb = ga.Wg + (ga.perBatchW ? (size_t)b * ga.O * C_ : 0);

    uint32_t smA = smem_u32(sm);

    auto load_stage = [&](int st, int k0) {
        uint32_t baseA = smA + st * ST_FLOATS * 4;
        uint32_t baseB = baseA + 4608 * 4;
#pragma unroll
        for (int i = 0; i < 4; i++) {
            int idx = tid + i * 256;
            int o = idx >> 3, kq = idx & 7;
            cp16(baseA + (o * 36 + kq * 4) * 4, Wb + (size_t)(oBase + o) * C_ + k0 + kq * 4);
        }
#pragma unroll
        for (int i = 0; i < 4; i++) {
            int idx = tid + i * 256;
            int k = idx >> 5, pq = idx & 31;
            cp16(baseB + (k * 136 + pq * 4) * 4, Xb + (size_t)(k0 + k) * HW_ + pBase + pq * 4);
        }
        cp_commit();
    };

    float acc[4][4][4] = {};
    float stS = 0.f, stQ = 0.f;
    int pl_stat = tid & 127, kh_stat = tid >> 7;

    load_stage(0, 0);
    load_stage(1, 32);
    for (int kc = 0; kc < 8; kc++) {
        if (kc + 2 < 8) { load_stage((kc + 2) % 3, (kc + 2) * 32); cp_wait<2>(); }
        else if (kc + 1 < 8) cp_wait<1>();
        else cp_wait<0>();
        __syncthreads();
        unsigned* sA = sm + (kc % 3) * ST_FLOATS;
        unsigned* sB = sA + 4608;
        if (ga.mode == 0) {
#pragma unroll
            for (int kk = 0; kk < 16; kk++) {
                float v = __uint_as_float(sB[(kh_stat * 16 + kk) * 136 + pl_stat]);
                stS += v; stQ += v * v;
            }
        }
#pragma unroll
        for (int s = 0; s < 32; s += 8) {
            unsigned afr[4][4];
#pragma unroll
            for (int mt = 0; mt < 4; mt++) {
                int ro = oW + mt * 16 + g;
                afr[mt][0] = sA[ro * 36 + s + tig];
                afr[mt][1] = sA[(ro + 8) * 36 + s + tig];
                afr[mt][2] = sA[ro * 36 + s + tig + 4];
                afr[mt][3] = sA[(ro + 8) * 36 + s + tig + 4];
            }
#pragma unroll
            for (int nt = 0; nt < 4; nt++) {
                int cp = pW + nt * 8 + g;
                unsigned b0 = sB[(s + tig) * 136 + cp];
                unsigned b1 = sB[(s + tig + 4) * 136 + cp];
#pragma unroll
                for (int mt = 0; mt < 4; mt++)
                    mma_tf32(acc[mt][nt], afr[mt], b0, b1);
            }
        }
        __syncthreads();
    }

    if (ga.mode == 0) {
        s_st[kh_stat][pl_stat] = stS;
        s_st[2 + kh_stat][pl_stat] = stQ;
        __syncthreads();
        float mu[4][2], iv[4][2];
#pragma unroll
        for (int nt = 0; nt < 4; nt++) {
#pragma unroll
            for (int u = 0; u < 2; u++) {
                int pl = pW + nt * 8 + 2 * tig + u;
                float s0 = s_st[0][pl] + s_st[1][pl];
                float q0 = s_st[2][pl] + s_st[3][pl];
                float m = s0 * (1.f / 256.f);
                float var = q0 * (1.f / 256.f) - m * m;
                mu[nt][u] = m;
                iv[nt][u] = rsqrtf(var + 1e-5f);
            }
        }
#pragma unroll
        for (int mt = 0; mt < 4; mt++) {
            int o0 = oBase + oW + mt * 16 + g;
            int o1 = o0 + 8;
            float rs0 = ga.rsum[o0], b0v = ga.bias[o0];
            float rs1 = ga.rsum[o1], b1v = ga.bias[o1];
#pragma unroll
            for (int nt = 0; nt < 4; nt++) {
                int p = pBase + pW + nt * 8 + 2 * tig;
                float2 r0, r1;
                r0.x = iv[nt][0] * (acc[mt][nt][0] - mu[nt][0] * rs0) + b0v;
                r0.y = iv[nt][1] * (acc[mt][nt][1] - mu[nt][1] * rs0) + b0v;
                r1.x = iv[nt][0] * (acc[mt][nt][2] - mu[nt][0] * rs1) + b1v;
                r1.y = iv[nt][1] * (acc[mt][nt][3] - mu[nt][1] * rs1) + b1v;
                *reinterpret_cast<float2*>(ga.Y + ((size_t)b * ga.O + o0) * HW_ + p) = r0;
                *reinterpret_cast<float2*>(ga.Y + ((size_t)b * ga.O + o1) * HW_ + p) = r1;
            }
        }
    } else {
        const float* pe = ga.pemb + (size_t)b * C_ * HW_;
#pragma unroll
        for (int mt = 0; mt < 4; mt++) {
            int o0 = oBase + oW + mt * 16 + g;
            int o1 = o0 + 8;
            float b0v = ga.bias[o0], b1v = ga.bias[o1];
#pragma unroll
            for (int nt = 0; nt < 4; nt++) {
                int p = pBase + pW + nt * 8 + 2 * tig;
                float2 p0 = *reinterpret_cast<const float2*>(pe + (size_t)o0 * HW_ + p);
                float2 p1 = *reinterpret_cast<const float2*>(pe + (size_t)o1 * HW_ + p);
                float2 r0, r1;
                r0.x = acc[mt][nt][0] + b0v + p0.x;
                r0.y = acc[mt][nt][1] + b0v + p0.y;
                r1.x = acc[mt][nt][2] + b1v + p1.x;
                r1.y = acc[mt][nt][3] + b1v + p1.y;
                *reinterpret_cast<float2*>(ga.Y + ((size_t)b * C_ + o0) * HW_ + p) = r0;
                *reinterpret_cast<float2*>(ga.Y + ((size_t)b * C_ + o1) * HW_ + p) = r1;
            }
        }
    }
}

// ---------------- vectorized depthwise 3x3 for q (+bias, +sumsq) -------------
// tile 16 rows x 128 cols; 4 cols/thread; padded smem rows (136 stride)
__global__ __launch_bounds__(256) void dwq_kernel(const float* __restrict__ X,
                                                  const float* __restrict__ w9,
                                                  const float* __restrict__ bias,
                                                  float* __restrict__ out,
                                                  float* __restrict__ ssq) {
    __shared__ float si[18][136];
    int b = blockIdx.z, c = blockIdx.y, r0 = blockIdx.x * 16;
    int tid = threadIdx.x;
    const float* Xc = X + ((size_t)(b * C_ + c)) * HW_;
    for (int i = tid; i < 18 * 34; i += 256) {
        int row = i / 34, q = i % 34;
        float4 v = make_float4(0.f, 0.f, 0.f, 0.f);
        int gr = r0 - 1 + row;
        if (q >= 1 && q <= 32 && gr >= 0 && gr < H_)
            v = *reinterpret_cast<const float4*>(Xc + (size_t)gr * W_ + (q - 1) * 4);
        *reinterpret_cast<float4*>(&si[row][q * 4]) = v;
    }
    float wk[9];
#pragma unroll
    for (int t = 0; t < 9; t++) wk[t] = __ldg(w9 + (size_t)c * 9 + t);
    float bv = __ldg(bias + c);
    __syncthreads();
    float* D = out + ((size_t)(b * C_ + c)) * HW_;
    float ss = 0.f;
    int row0 = tid >> 5, c0 = (tid & 31) * 4;
#pragma unroll
    for (int it = 0; it < 2; it++) {
        int row = row0 + it * 8;
        float4 o = make_float4(bv, bv, bv, bv);
#pragma unroll
        for (int dr = 0; dr < 3; dr++)
            stencil4(si[row + dr], c0, wk[dr * 3], wk[dr * 3 + 1], wk[dr * 3 + 2], o);
        *reinterpret_cast<float4*>(D + (size_t)(r0 + row) * W_ + c0) = o;
        ss += o.x * o.x + o.y * o.y + o.z * o.z + o.w * o.w;
    }
#pragma unroll
    for (int d = 16; d > 0; d >>= 1) ss += __shfl_down_sync(0xffffffffu, ss, d);
    if ((tid & 31) == 0) atomicAdd(&ssq[b * C_ + c], ss);
}

// ---------------- merged kv dwconv + positional branch ------------------------
// per (b, c, 16-row tile): k = dw(kv_pre_k)+bias -> g_k (+sumsq)
//                          v = dw(kv_pre_v)+bias (with 2-row halo) -> g_v
//                          pemb = dw(gelu(dw(v,pe1)),pe2) + hx -> g_bufA
__global__ __launch_bounds__(256) void kvpe_kernel(const float* __restrict__ hx,
                                                   const float* __restrict__ kvw9,
                                                   const float* __restrict__ kvb,
                                                   const float* __restrict__ pe1,
                                                   const float* __restrict__ pe2) {
    __shared__ float ski[18][136];
    __shared__ float svi[22][136];
    __shared__ float sv[20][136];
    __shared__ float st1[18][136];
    int b = blockIdx.z, c = blockIdx.y, r0 = blockIdx.x * 16;
    int tid = threadIdx.x;
    const float* Kc = g_bufB + ((size_t)(b * 2 * C_ + c)) * HW_;
    const float* Vc = g_bufB + ((size_t)(b * 2 * C_ + C_ + c)) * HW_;

    for (int i = tid; i < 18 * 34; i += 256) {
        int row = i / 34, q = i % 34;
        float4 v = make_float4(0.f, 0.f, 0.f, 0.f);
        int gr = r0 - 1 + row;
        if (q >= 1 && q <= 32 && gr >= 0 && gr < H_)
            v = *reinterpret_cast<const float4*>(Kc + (size_t)gr * W_ + (q - 1) * 4);
        *reinterpret_cast<float4*>(&ski[row][q * 4]) = v;
    }
    for (int i = tid; i < 22 * 34; i += 256) {
        int row = i / 34, q = i % 34;
        float4 v = make_float4(0.f, 0.f, 0.f, 0.f);
        int gr = r0 - 3 + row;
        if (q >= 1 && q <= 32 && gr >= 0 && gr < H_)
            v = *reinterpret_cast<const float4*>(Vc + (size_t)gr * W_ + (q - 1) * 4);
        *reinterpret_cast<float4*>(&svi[row][q * 4]) = v;
    }
    // pre-zero sv and st1 (pads + out-of-image rows stay zero)
    for (int i = tid; i < (20 + 18) * 34; i += 256) {
        int row = i / 34, q = i % 34;
        float4 z = make_float4(0.f, 0.f, 0.f, 0.f);
        if (row < 20) *reinterpret_cast<float4*>(&sv[row][q * 4]) = z;
        else *reinterpret_cast<float4*>(&st1[row - 20][q * 4]) = z;
    }
    float wkk[9], wkv[9], w1[9], w2[9];
#pragma unroll
    for (int t = 0; t < 9; t++) {
        wkk[t] = __ldg(kvw9 + (size_t)c * 9 + t);
        wkv[t] = __ldg(kvw9 + (size_t)(C_ + c) * 9 + t);
        w1[t] = __ldg(pe1 + (size_t)c * 9 + t);
        w2[t] = __ldg(pe2 + (size_t)c * 9 + t);
    }
    float bk = __ldg(kvb + c);
    float bvv = __ldg(kvb + C_ + c);
    __syncthreads();

    int row0 = tid >> 5, c0 = (tid & 31) * 4;

    // ---- k (16 rows) ----
    float* Dk = g_k + ((size_t)(b * C_ + c)) * HW_;
    float ss = 0.f;
#pragma unroll
    for (int it = 0; it < 2; it++) {
        int row = row0 + it * 8;
        float4 o = make_float4(bk, bk, bk, bk);
#pragma unroll
        for (int dr = 0; dr < 3; dr++)
            stencil4(ski[row + dr], c0, wkk[dr * 3], wkk[dr * 3 + 1], wkk[dr * 3 + 2], o);
        *reinterpret_cast<float4*>(Dk + (size_t)(r0 + row) * W_ + c0) = o;
        ss += o.x * o.x + o.y * o.y + o.z * o.z + o.w * o.w;
    }
#pragma unroll
    for (int d = 16; d > 0; d >>= 1) ss += __shfl_down_sync(0xffffffffu, ss, d);
    if ((tid & 31) == 0) atomicAdd(&g_ss[B_ * C_ + b * C_ + c], ss);

    // ---- v (20 rows incl. halo) ----
    float* Dv = g_v + ((size_t)(b * C_ + c)) * HW_;
    for (int i = tid; i < 20 * 32; i += 256) {
        int row = i >> 5, cc = (i & 31) * 4;
        int gr = r0 - 2 + row;
        if (gr < 0 || gr >= H_) continue;
        float4 o = make_float4(bvv, bvv, bvv, bvv);
#pragma unroll
        for (int dr = 0; dr < 3; dr++)
            stencil4(svi[row + dr], cc, wkv[dr * 3], wkv[dr * 3 + 1], wkv[dr * 3 + 2], o);
        *reinterpret_cast<float4*>(&sv[row][4 + cc]) = o;
        if (row >= 2 && row < 18)
            *reinterpret_cast<float4*>(Dv + (size_t)gr * W_ + cc) = o;
    }
    __syncthreads();

    // ---- t1 = gelu(dw(v, pe1)) (18 rows incl. halo) ----
    for (int i = tid; i < 18 * 32; i += 256) {
        int row = i >> 5, cc = (i & 31) * 4;
        int gr = r0 - 1 + row;
        if (gr < 0 || gr >= H_) continue;
        float4 o = make_float4(0.f, 0.f, 0.f, 0.f);
#pragma unroll
        for (int dr = 0; dr < 3; dr++)
            stencil4(sv[row + dr], cc, w1[dr * 3], w1[dr * 3 + 1], w1[dr * 3 + 2], o);
        o.x = gelu_tanh(o.x); o.y = gelu_tanh(o.y);
        o.z = gelu_tanh(o.z); o.w = gelu_tanh(o.w);
        *reinterpret_cast<float4*>(&st1[row][4 + cc]) = o;
    }
    __syncthreads();

    // ---- pemb = dw(t1, pe2) + hx (16 rows) -> g_bufA ----
    float* Dp = g_bufA + ((size_t)(b * C_ + c)) * HW_;
    const float* Hc = hx + ((size_t)(b * C_ + c)) * HW_;
#pragma unroll
    for (int it = 0; it < 2; it++) {
        int row = row0 + it * 8;
        float4 o = make_float4(0.f, 0.f, 0.f, 0.f);
#pragma unroll
        for (int dr = 0; dr < 3; dr++)
            stencil4(st1[row + dr], c0, w2[dr * 3], w2[dr * 3 + 1], w2[dr * 3 + 2], o);
        float4 hv = *reinterpret_cast<const float4*>(Hc + (size_t)(r0 + row) * W_ + c0);
        o.x += hv.x; o.y += hv.y; o.z += hv.z; o.w += hv.w;
        *reinterpret_cast<float4*>(Dp + (size_t)(r0 + row) * W_ + c0) = o;
    }
}

// ---------------- gram via tf32 mma: 32x32 per (b,h), split-K=4 --------------
__global__ __launch_bounds__(256) void gram_mma() {
    __shared__ float sbuf[2 * 32 * 132];
    float* sq = sbuf;
    float* sk = sbuf + 32 * 132;
    int seg = blockIdx.x, h = blockIdx.y, b = blockIdx.z;
    const float* Q = g_q + ((size_t)(b * C_ + h * HD_)) * HW_;
    const float* K = g_k + ((size_t)(b * C_ + h * HD_)) * HW_;
    int tid = threadIdx.x, wid = tid >> 5, lane = tid & 31;
    int g = lane >> 2, tig = lane & 3;
    float acc[2][4][4] = {};
    int n0 = seg * (HW_ / GSEG);
    for (int ch = 0; ch < (HW_ / GSEG) / 128; ch++) {
        int base = n0 + ch * 128;
        for (int i = tid; i < 32 * 32; i += 256) {
            int row = i >> 5, c4 = i & 31;
            *reinterpret_cast<float4*>(&sq[row * 132 + c4 * 4]) =
                *reinterpret_cast<const float4*>(Q + (size_t)row * HW_ + base + c4 * 4);
            *reinterpret_cast<float4*>(&sk[row * 132 + c4 * 4]) =
                *reinterpret_cast<const float4*>(K + (size_t)row * HW_ + base + c4 * 4);
        }
        __syncthreads();
        int kl0 = wid * 16;
#pragma unroll
        for (int s = 0; s < 2; s++) {
            int kl = kl0 + s * 8;
            unsigned afr[2][4];
#pragma unroll
            for (int mt = 0; mt < 2; mt++) {
                int r = mt * 16 + g;
                afr[mt][0] = __float_as_uint(sq[r * 132 + kl + tig]);
                afr[mt][1] = __float_as_uint(sq[(r + 8) * 132 + kl + tig]);
                afr[mt][2] = __float_as_uint(sq[r * 132 + kl + tig + 4]);
                afr[mt][3] = __float_as_uint(sq[(r + 8) * 132 + kl + tig + 4]);
            }
#pragma unroll
            for (int nt = 0; nt < 4; nt++) {
                unsigned b0 = __float_as_uint(sk[(nt * 8 + g) * 132 + kl + tig]);
                unsigned b1 = __float_as_uint(sk[(nt * 8 + g) * 132 + kl + tig + 4]);
#pragma unroll
                for (int mt = 0; mt < 2; mt++)
                    mma_tf32(acc[mt][nt], afr[mt], b0, b1);
            }
        }
        __syncthreads();
    }
    float* red = sbuf;
#pragma unroll
    for (int mt = 0; mt < 2; mt++)
#pragma unroll
        for (int nt = 0; nt < 4; nt++) {
            int r = mt * 16 + g, cl = nt * 8 + 2 * tig;
            red[wid * 1024 + r * 32 + cl] = acc[mt][nt][0];
            red[wid * 1024 + r * 32 + cl + 1] = acc[mt][nt][1];
            red[wid * 1024 + (r + 8) * 32 + cl] = acc[mt][nt][2];
            red[wid * 1024 + (r + 8) * 32 + cl + 1] = acc[mt][nt][3];
        }
    __syncthreads();
    float* outp = g_part + ((size_t)(b * HEADS_ + h) * GSEG + seg) * 1024;
    for (int i = tid; i < 1024; i += 256) {
        float s = 0.f;
#pragma unroll
        for (int w = 0; w < 8; w++) s += red[w * 1024 + i];
        outp[i] = s;
    }
}

// ---------------- softmax with fused q/k norm scales + temperature -----------
__global__ void softmax_kernel(const float* __restrict__ temp) {
    int bh = blockIdx.x;
    int b = bh >> 3, h = bh & 7;
    int i = threadIdx.x;
    float qs = 1.f / fmaxf(sqrtf(g_ss[b * C_ + h * HD_ + i]), 1e-12f);
    float T = __ldg(temp + h);
    float v[32];
    float mx = -1e30f;
#pragma unroll 4
    for (int j = 0; j < 32; j++) {
        float s = 0.f;
#pragma unroll
        for (int seg = 0; seg < GSEG; seg++)
            s += g_part[((size_t)bh * GSEG + seg) * 1024 + i * 32 + j];
        float ks = 1.f / fmaxf(sqrtf(g_ss[B_ * C_ + b * C_ + h * HD_ + j]), 1e-12f);
        float val = s * qs * ks * T;
        v[j] = val;
        mx = fmaxf(mx, val);
    }
    float sum = 0.f;
#pragma unroll
    for (int j = 0; j < 32; j++) {
        v[j] = expf(v[j] - mx);
        sum += v[j];
    }
    float inv = 1.f / sum;
#pragma unroll
    for (int j = 0; j < 32; j++) g_attn[bh * 1024 + i * 32 + j] = v[j] * inv;
}

// ---------------- M[b] = ao_w @ blockdiag(attn[b]) ---------------------------
__global__ void buildM_kernel(const float* __restrict__ ao_w) {
    int h = blockIdx.x, b = blockIdx.y;
    int tid = threadIdx.x;
    __shared__ float sa[32][33];
#pragma unroll
    for (int t = 0; t < 4; t++) {
        int idx = tid + t * 256;
        sa[idx >> 5][idx & 31] = g_attn[(b * HEADS_ + h) * 1024 + idx];
    }
    __syncthreads();
    float wreg[32];
#pragma unroll
    for (int c = 0; c < 32; c++) wreg[c] = ao_w[(size_t)tid * C_ + h * HD_ + c];
#pragma unroll 4
    for (int d = 0; d < 32; d++) {
        float m = 0.f;
#pragma unroll
        for (int c = 0; c < 32; c++) m += wreg[c] * sa[c][d];
        g_M[((size_t)(b * C_) + tid) * C_ + h * HD_ + d] = m;
    }
}

// -----------------------------------------------------------------------------
extern "C" void kernel_launch(void* const* d_in, const int* in_sizes, int n_in,
                              void* d_out, int out_size) {
    const float* x = (const float*)d_in[0];
    const float* hx = (const float*)d_in[1];
    const float* ln1_w = (const float*)d_in[2];
    const float* ln1_b = (const float*)d_in[3];
    const float* ln2_w = (const float*)d_in[4];
    const float* ln2_b = (const float*)d_in[5];
    const float* q_w = (const float*)d_in[6];
    const float* q_b = (const float*)d_in[7];
    const float* q_dw_w = (const float*)d_in[8];
    const float* q_dw_b = (const float*)d_in[9];
    const float* kv_w = (const float*)d_in[10];
    const float* kv_b = (const float*)d_in[11];
    const float* kv_dw_w = (const float*)d_in[12];
    const float* kv_dw_b = (const float*)d_in[13];
    const float* ao_w = (const float*)d_in[14];
    const float* ao_b = (const float*)d_in[15];
    const float* pe1_w = (const float*)d_in[16];
    const float* pe2_w = (const float*)d_in[17];
    const float* temperature = (const float*)d_in[18];
    float* out = (float*)d_out;

    float *p_Wq, *p_Wkv, *p_bq, *p_bkv, *p_rsq, *p_rskv;
    float *p_bufA, *p_bufB, *p_q, *p_v, *p_M, *p_ss;
    cudaGetSymbolAddress((void**)&p_Wq, g_Wq);
    cudaGetSymbolAddress((void**)&p_Wkv, g_Wkv);
    cudaGetSymbolAddress((void**)&p_bq, g_bq);
    cudaGetSymbolAddress((void**)&p_bkv, g_bkv);
    cudaGetSymbolAddress((void**)&p_rsq, g_rsq);
    cudaGetSymbolAddress((void**)&p_rskv, g_rskv);
    cudaGetSymbolAddress((void**)&p_bufA, g_bufA);
    cudaGetSymbolAddress((void**)&p_bufB, g_bufB);
    cudaGetSymbolAddress((void**)&p_q, g_q);
    cudaGetSymbolAddress((void**)&p_v, g_v);
    cudaGetSymbolAddress((void**)&p_M, g_M);
    cudaGetSymbolAddress((void**)&p_ss, g_ss);

    const int gemm_smem = 3 * ST_FLOATS * 4;   // 107520 bytes
    cudaFuncSetAttribute(gemm_tc_kernel, cudaFuncAttributeMaxDynamicSharedMemorySize, gemm_smem);

    // 1. fold LN into weights; zero sumsq accumulators
    prep_w_kernel<<<3 * C_, 256>>>(q_w, q_b, ln1_w, ln1_b, kv_w, kv_b, ln2_w, ln2_b);

    // 2. q_pre = conv1x1(ln(x)) -> bufA ; kv_pre = conv1x1(ln(hx)) -> bufB
    {
        GemmArgs ga{};
        ga.X = x; ga.Wg = p_Wq; ga.bias = p_bq; ga.rsum = p_rsq;
        ga.Y = p_bufA; ga.O = C_; ga.mode = 0; ga.perBatchW = 0;
        gemm_tc_kernel<<<dim3(HW_ / 128, C_ / 128, B_), 256, gemm_smem>>>(ga);
    }
    {
        GemmArgs ga{};
        ga.X = hx; ga.Wg = p_Wkv; ga.bias = p_bkv; ga.rsum = p_rskv;
        ga.Y = p_bufB; ga.O = 2 * C_; ga.mode = 0; ga.perBatchW = 0;
        gemm_tc_kernel<<<dim3(HW_ / 128, 2 * C_ / 128, B_), 256, gemm_smem>>>(ga);
    }

    // 3. q dwconv (vectorized) -> g_q  [must precede kvpe: bufA reused for pemb]
    dwq_kernel<<<dim3(8, C_, B_), 256>>>(p_bufA, q_dw_w, q_dw_b, p_q, p_ss);

    // 4. merged kv dwconv + positional branch -> g_k, g_v, pemb->bufA
    kvpe_kernel<<<dim3(8, C_, B_), 256>>>(hx, kv_dw_w, kv_dw_b, pe1_w, pe2_w);

    // 5. gram (tf32 mma, split-K=4), softmax with fused norms
    gram_mma<<<dim3(GSEG, HEADS_, B_), 256>>>();
    softmax_kernel<<<B_ * HEADS_, 32>>>(temperature);

    // 6. fold attn into output projection; final fused GEMM (+pemb from bufA)
    buildM_kernel<<<dim3(HEADS_, B_), 256>>>(ao_w);
    {
        GemmArgs ga{};
        ga.X = p_v; ga.Wg = p_M; ga.bias = ao_b; ga.pemb = p_bufA;
        ga.Y = out; ga.O = C_; ga.mode = 1; ga.perBatchW = 1;
        gemm_tc_kernel<<<dim3(HW_ / 128, C_ / 128, B_), 256, gemm_smem>>>(ga);
    }
}

// round 5
// speedup vs baseline: 1.0762x; 1.0762x over previous
#include <cuda_runtime.h>
#include <cuda_bf16.h>
#include <math.h>
#include <stdint.h>

#define B_ 8
#define C_ 256
#define H_ 128
#define W_ 128
#define HW_ 16384
#define HEADS_ 8
#define HD_ 32
#define GSEG 4

typedef __nv_bfloat16 bf16;
typedef __nv_bfloat162 bf162;

// ---------------- scratch (device globals; no allocation allowed) ------------
__device__ bf16 g_bufA[B_ * C_ * HW_];           // q_pre
__device__ bf16 g_bufB[B_ * 2 * C_ * HW_];       // kv_pre
__device__ bf16 g_q[B_ * C_ * HW_];
__device__ bf16 g_k[B_ * C_ * HW_];
__device__ bf16 g_v[B_ * C_ * HW_];
__device__ bf16 g_pe[B_ * C_ * HW_];             // pemb (WITHOUT hx)
__device__ float g_Wq[C_ * C_];
__device__ float g_Wkv[2 * C_ * C_];
__device__ float g_bq[C_];
__device__ float g_bkv[2 * C_];
__device__ float g_rsq[C_];
__device__ float g_rskv[2 * C_];
__device__ float g_ss[2 * B_ * C_];
__device__ float g_part[B_ * HEADS_ * GSEG * 1024];
__device__ float g_attn[B_ * HEADS_ * 1024];
__device__ float g_M[B_ * C_ * C_];

// ---------------- helpers ------------------------------------------------
__device__ __forceinline__ void mma_tf32(float* c, const unsigned* a, unsigned b0, unsigned b1) {
    asm volatile(
        "mma.sync.aligned.m16n8k8.row.col.f32.tf32.tf32.f32 "
        "{%0,%1,%2,%3}, {%4,%5,%6,%7}, {%8,%9}, {%0,%1,%2,%3};\n"
        : "+f"(c[0]), "+f"(c[1]), "+f"(c[2]), "+f"(c[3])
        : "r"(a[0]), "r"(a[1]), "r"(a[2]), "r"(a[3]), "r"(b0), "r"(b1));
}
__device__ __forceinline__ void mma_bf16(float* c, const unsigned* a, unsigned b0, unsigned b1) {
    asm volatile(
        "mma.sync.aligned.m16n8k16.row.col.f32.bf16.bf16.f32 "
        "{%0,%1,%2,%3}, {%4,%5,%6,%7}, {%8,%9}, {%0,%1,%2,%3};\n"
        : "+f"(c[0]), "+f"(c[1]), "+f"(c[2]), "+f"(c[3])
        : "r"(a[0]), "r"(a[1]), "r"(a[2]), "r"(a[3]), "r"(b0), "r"(b1));
}
__device__ __forceinline__ uint32_t smem_u32(const void* p) {
    return (uint32_t)__cvta_generic_to_shared(p);
}
__device__ __forceinline__ void cp16(uint32_t dst, const void* src) {
    asm volatile("cp.async.cg.shared.global [%0], [%1], 16;\n" :: "r"(dst), "l"(src));
}
__device__ __forceinline__ void cp_commit() { asm volatile("cp.async.commit_group;\n"); }
template <int N>
__device__ __forceinline__ void cp_wait() { asm volatile("cp.async.wait_group %0;\n" ::"n"(N)); }

__device__ __forceinline__ float gelu_tanh(float s) {
    float x3 = s * s * s;
    return 0.5f * s * (1.f + tanhf(0.7978845608028654f * (s + 0.044715f * x3)));
}
__device__ __forceinline__ void u4_to_f8(uint4 u, float4& lo, float4& hi) {
    bf162 h0, h1, h2, h3;
    h0 = *reinterpret_cast<bf162*>(&u.x);
    h1 = *reinterpret_cast<bf162*>(&u.y);
    h2 = *reinterpret_cast<bf162*>(&u.z);
    h3 = *reinterpret_cast<bf162*>(&u.w);
    float2 f0 = __bfloat1622float2(h0), f1 = __bfloat1622float2(h1);
    float2 f2 = __bfloat1622float2(h2), f3 = __bfloat1622float2(h3);
    lo = make_float4(f0.x, f0.y, f1.x, f1.y);
    hi = make_float4(f2.x, f2.y, f3.x, f3.y);
}
__device__ __forceinline__ uint2 f4_to_u2(float4 v) {
    bf162 a = __floats2bfloat162_rn(v.x, v.y);
    bf162 b = __floats2bfloat162_rn(v.z, v.w);
    uint2 r;
    r.x = *reinterpret_cast<unsigned*>(&a);
    r.y = *reinterpret_cast<unsigned*>(&b);
    return r;
}

// 3x3 row-tap over padded smem row (data at +4, zeros at 0..3 / 132..135)
__device__ __forceinline__ void stencil4(const float* R, int c0, float w0, float w1, float w2,
                                         float4& o) {
    float4 m = *reinterpret_cast<const float4*>(R + 4 + c0);
    float l = R[3 + c0];
    float r = R[8 + c0];
    o.x += w0 * l + w1 * m.x + w2 * m.y;
    o.y += w0 * m.x + w1 * m.y + w2 * m.z;
    o.z += w0 * m.y + w1 * m.z + w2 * m.w;
    o.w += w0 * m.z + w1 * m.w + w2 * r;
}

// ---------------- weight prep: fold LN gamma/beta into conv1x1 ---------------
__global__ void prep_w_kernel(const float* __restrict__ qw, const float* __restrict__ qb,
                              const float* __restrict__ ln1w, const float* __restrict__ ln1b,
                              const float* __restrict__ kvw, const float* __restrict__ kvb,
                              const float* __restrict__ ln2w, const float* __restrict__ ln2b) {
    int r = blockIdx.x;
    int tid = threadIdx.x;
    if (r < 16) g_ss[r * 256 + tid] = 0.f;
    const float *w, *lnw, *lnb;
    float cb;
    float *dW, *dB, *dR;
    if (r < C_) {
        int o = r;
        w = qw + (size_t)o * C_; lnw = ln1w; lnb = ln1b; cb = qb[o];
        dW = g_Wq + (size_t)o * C_; dB = g_bq + o; dR = g_rsq + o;
    } else {
        int o = r - C_;
        w = kvw + (size_t)o * C_; lnw = ln2w; lnb = ln2b; cb = kvb[o];
        dW = g_Wkv + (size_t)o * C_; dB = g_bkv + o; dR = g_rskv + o;
    }
    float wv = w[tid];
    float we = wv * lnw[tid];
    dW[tid] = we;
    __shared__ float sh1[256], sh2[256];
    sh1[tid] = we;
    sh2[tid] = wv * lnb[tid];
    __syncthreads();
    for (int s = 128; s > 0; s >>= 1) {
        if (tid < s) { sh1[tid] += sh1[tid + s]; sh2[tid] += sh2[tid + s]; }
        __syncthreads();
    }
    if (tid == 0) { *dR = sh1[0]; *dB = cb + sh2[0]; }
}

// ========= LN-fused tensor-core GEMM (tf32, cp.async 3-stage, bf16 out) ======
// grid: (O/128, HW/128, B) -- o fastest for L2 reuse of X across o-tiles
struct GemmArgs {
    const float* X;
    const float* Wg;
    const float* bias;
    const float* rsum;
    bf16* Yh;
    int O;
};

#define ST_FLOATS 8960   // per stage: A 128*36=4608 + B 32*136=4352

__global__ __launch_bounds__(256, 2) void gemm_ln_kernel(GemmArgs ga) {
    extern __shared__ unsigned sm[];
    __shared__ float s_st[4][128];
    int b = blockIdx.z;
    int oBase = blockIdx.x * 128;
    int pBase = blockIdx.y * 128;
    int tid = threadIdx.x;
    int wid = tid >> 5, lane = tid & 31;
    int g = lane >> 2, tig = lane & 3;
    int oW = (wid >> 2) * 64;
    int pW = (wid & 3) * 32;

    const float* Xb = ga.X + (size_t)b * C_ * HW_;
    const float* Wb = ga.Wg;
    uint32_t smA = smem_u32(sm);

    auto load_stage = [&](int st, int k0) {
        uint32_t baseA = smA + st * ST_FLOATS * 4;
        uint32_t baseB = baseA + 4608 * 4;
#pragma unroll
        for (int i = 0; i < 4; i++) {
            int idx = tid + i * 256;
            int o = idx >> 3, kq = idx & 7;
            cp16(baseA + (o * 36 + kq * 4) * 4, Wb + (size_t)(oBase + o) * C_ + k0 + kq * 4);
        }
#pragma unroll
        for (int i = 0; i < 4; i++) {
            int idx = tid + i * 256;
            int k = idx >> 5, pq = idx & 31;
            cp16(baseB + (k * 136 + pq * 4) * 4, Xb + (size_t)(k0 + k) * HW_ + pBase + pq * 4);
        }
        cp_commit();
    };

    float acc[4][4][4] = {};
    float stS = 0.f, stQ = 0.f;
    int pl_stat = tid & 127, kh_stat = tid >> 7;

    load_stage(0, 0);
    load_stage(1, 32);
    for (int kc = 0; kc < 8; kc++) {
        if (kc + 2 < 8) { load_stage((kc + 2) % 3, (kc + 2) * 32); cp_wait<2>(); }
        else if (kc + 1 < 8) cp_wait<1>();
        else cp_wait<0>();
        __syncthreads();
        unsigned* sA = sm + (kc % 3) * ST_FLOATS;
        unsigned* sB = sA + 4608;
#pragma unroll
        for (int kk = 0; kk < 16; kk++) {
            float v = __uint_as_float(sB[(kh_stat * 16 + kk) * 136 + pl_stat]);
            stS += v; stQ += v * v;
        }
#pragma unroll
        for (int s = 0; s < 32; s += 8) {
            unsigned afr[4][4];
#pragma unroll
            for (int mt = 0; mt < 4; mt++) {
                int ro = oW + mt * 16 + g;
                afr[mt][0] = sA[ro * 36 + s + tig];
                afr[mt][1] = sA[(ro + 8) * 36 + s + tig];
                afr[mt][2] = sA[ro * 36 + s + tig + 4];
                afr[mt][3] = sA[(ro + 8) * 36 + s + tig + 4];
            }
#pragma unroll
            for (int nt = 0; nt < 4; nt++) {
                int cp = pW + nt * 8 + g;
                unsigned b0 = sB[(s + tig) * 136 + cp];
                unsigned b1 = sB[(s + tig + 4) * 136 + cp];
#pragma unroll
                for (int mt = 0; mt < 4; mt++)
                    mma_tf32(acc[mt][nt], afr[mt], b0, b1);
            }
        }
        __syncthreads();
    }

    s_st[kh_stat][pl_stat] = stS;
    s_st[2 + kh_stat][pl_stat] = stQ;
    __syncthreads();
    float mu[4][2], iv[4][2];
#pragma unroll
    for (int nt = 0; nt < 4; nt++) {
#pragma unroll
        for (int u = 0; u < 2; u++) {
            int pl = pW + nt * 8 + 2 * tig + u;
            float s0 = s_st[0][pl] + s_st[1][pl];
            float q0 = s_st[2][pl] + s_st[3][pl];
            float m = s0 * (1.f / 256.f);
            float var = q0 * (1.f / 256.f) - m * m;
            mu[nt][u] = m;
            iv[nt][u] = rsqrtf(var + 1e-5f);
        }
    }
#pragma unroll
    for (int mt = 0; mt < 4; mt++) {
        int o0 = oBase + oW + mt * 16 + g;
        int o1 = o0 + 8;
        float rs0 = ga.rsum[o0], b0v = ga.bias[o0];
        float rs1 = ga.rsum[o1], b1v = ga.bias[o1];
#pragma unroll
        for (int nt = 0; nt < 4; nt++) {
            int p = pBase + pW + nt * 8 + 2 * tig;
            bf162 r0 = __floats2bfloat162_rn(
                iv[nt][0] * (acc[mt][nt][0] - mu[nt][0] * rs0) + b0v,
                iv[nt][1] * (acc[mt][nt][1] - mu[nt][1] * rs0) + b0v);
            bf162 r1 = __floats2bfloat162_rn(
                iv[nt][0] * (acc[mt][nt][2] - mu[nt][0] * rs1) + b1v,
                iv[nt][1] * (acc[mt][nt][3] - mu[nt][1] * rs1) + b1v);
            *reinterpret_cast<bf162*>(ga.Yh + ((size_t)b * ga.O + o0) * HW_ + p) = r0;
            *reinterpret_cast<bf162*>(ga.Yh + ((size_t)b * ga.O + o1) * HW_ + p) = r1;
        }
    }
}

// ---------------- depthwise 3x3 for q (bf16 in/out, +bias, +sumsq) -----------
__global__ __launch_bounds__(256) void dwq_kernel(const bf16* __restrict__ X,
                                                  const float* __restrict__ w9,
                                                  const float* __restrict__ bias,
                                                  bf16* __restrict__ out,
                                                  float* __restrict__ ssq) {
    __shared__ float si[18][136];
    int b = blockIdx.z, c = blockIdx.y, r0 = blockIdx.x * 16;
    int tid = threadIdx.x;
    const bf16* Xc = X + ((size_t)(b * C_ + c)) * HW_;
    float4 z4 = make_float4(0.f, 0.f, 0.f, 0.f);
    for (int i = tid; i < 18 * 34; i += 256)
        *reinterpret_cast<float4*>(&si[i / 34][(i % 34) * 4]) = z4;
    __syncthreads();
    for (int i = tid; i < 18 * 16; i += 256) {
        int row = i >> 4, c8 = (i & 15) * 8, gr = r0 - 1 + row;
        if (gr >= 0 && gr < H_) {
            uint4 u = *reinterpret_cast<const uint4*>(Xc + (size_t)gr * W_ + c8);
            float4 lo, hi;
            u4_to_f8(u, lo, hi);
            *reinterpret_cast<float4*>(&si[row][4 + c8]) = lo;
            *reinterpret_cast<float4*>(&si[row][8 + c8]) = hi;
        }
    }
    float wk[9];
#pragma unroll
    for (int t = 0; t < 9; t++) wk[t] = __ldg(w9 + (size_t)c * 9 + t);
    float bv = __ldg(bias + c);
    __syncthreads();
    bf16* D = out + ((size_t)(b * C_ + c)) * HW_;
    float ss = 0.f;
    int row0 = tid >> 5, c0 = (tid & 31) * 4;
#pragma unroll
    for (int it = 0; it < 2; it++) {
        int row = row0 + it * 8;
        float4 o = make_float4(bv, bv, bv, bv);
#pragma unroll
        for (int dr = 0; dr < 3; dr++)
            stencil4(si[row + dr], c0, wk[dr * 3], wk[dr * 3 + 1], wk[dr * 3 + 2], o);
        *reinterpret_cast<uint2*>(D + (size_t)(r0 + row) * W_ + c0) = f4_to_u2(o);
        ss += o.x * o.x + o.y * o.y + o.z * o.z + o.w * o.w;
    }
#pragma unroll
    for (int d = 16; d > 0; d >>= 1) ss += __shfl_down_sync(0xffffffffu, ss, d);
    if ((tid & 31) == 0) atomicAdd(&ssq[b * C_ + c], ss);
}

// ---------------- merged kv dwconv + positional branch (bf16) -----------------
// k -> g_k (+sumsq); v -> g_v; pemb (NO hx) -> g_pe
__global__ __launch_bounds__(256) void kvpe_kernel(const float* __restrict__ kvw9,
                                                   const float* __restrict__ kvb,
                                                   const float* __restrict__ pe1,
                                                   const float* __restrict__ pe2) {
    __shared__ float ski[18][136];
    __shared__ float svi[22][136];
    __shared__ float sv[20][136];
    __shared__ float st1[18][136];
    int b = blockIdx.z, c = blockIdx.y, r0 = blockIdx.x * 16;
    int tid = threadIdx.x;
    const bf16* Kc = g_bufB + ((size_t)(b * 2 * C_ + c)) * HW_;
    const bf16* Vc = g_bufB + ((size_t)(b * 2 * C_ + C_ + c)) * HW_;
    float4 z4 = make_float4(0.f, 0.f, 0.f, 0.f);
    for (int i = tid; i < 18 * 34; i += 256)
        *reinterpret_cast<float4*>(&ski[i / 34][(i % 34) * 4]) = z4;
    for (int i = tid; i < 22 * 34; i += 256)
        *reinterpret_cast<float4*>(&svi[i / 34][(i % 34) * 4]) = z4;
    for (int i = tid; i < 20 * 34; i += 256)
        *reinterpret_cast<float4*>(&sv[i / 34][(i % 34) * 4]) = z4;
    for (int i = tid; i < 18 * 34; i += 256)
        *reinterpret_cast<float4*>(&st1[i / 34][(i % 34) * 4]) = z4;
    __syncthreads();
    for (int i = tid; i < 18 * 16; i += 256) {
        int row = i >> 4, c8 = (i & 15) * 8, gr = r0 - 1 + row;
        if (gr >= 0 && gr < H_) {
            uint4 u = *reinterpret_cast<const uint4*>(Kc + (size_t)gr * W_ + c8);
            float4 lo, hi;
            u4_to_f8(u, lo, hi);
            *reinterpret_cast<float4*>(&ski[row][4 + c8]) = lo;
            *reinterpret_cast<float4*>(&ski[row][8 + c8]) = hi;
        }
    }
    for (int i = tid; i < 22 * 16; i += 256) {
        int row = i >> 4, c8 = (i & 15) * 8, gr = r0 - 3 + row;
        if (gr >= 0 && gr < H_) {
            uint4 u = *reinterpret_cast<const uint4*>(Vc + (size_t)gr * W_ + c8);
            float4 lo, hi;
            u4_to_f8(u, lo, hi);
            *reinterpret_cast<float4*>(&svi[row][4 + c8]) = lo;
            *reinterpret_cast<float4*>(&svi[row][8 + c8]) = hi;
        }
    }
    float wkk[9], wkv[9], w1[9], w2[9];
#pragma unroll
    for (int t = 0; t < 9; t++) {
        wkk[t] = __ldg(kvw9 + (size_t)c * 9 + t);
        wkv[t] = __ldg(kvw9 + (size_t)(C_ + c) * 9 + t);
        w1[t] = __ldg(pe1 + (size_t)c * 9 + t);
        w2[t] = __ldg(pe2 + (size_t)c * 9 + t);
    }
    float bk = __ldg(kvb + c);
    float bvv = __ldg(kvb + C_ + c);
    __syncthreads();

    int row0 = tid >> 5, c0 = (tid & 31) * 4;

    // ---- k (16 rows) ----
    bf16* Dk = g_k + ((size_t)(b * C_ + c)) * HW_;
    float ss = 0.f;
#pragma unroll
    for (int it = 0; it < 2; it++) {
        int row = row0 + it * 8;
        float4 o = make_float4(bk, bk, bk, bk);
#pragma unroll
        for (int dr = 0; dr < 3; dr++)
            stencil4(ski[row + dr], c0, wkk[dr * 3], wkk[dr * 3 + 1], wkk[dr * 3 + 2], o);
        *reinterpret_cast<uint2*>(Dk + (size_t)(r0 + row) * W_ + c0) = f4_to_u2(o);
        ss += o.x * o.x + o.y * o.y + o.z * o.z + o.w * o.w;
    }
#pragma unroll
    for (int d = 16; d > 0; d >>= 1) ss += __shfl_down_sync(0xffffffffu, ss, d);
    if ((tid & 31) == 0) atomicAdd(&g_ss[B_ * C_ + b * C_ + c], ss);

    // ---- v (20 rows incl. halo) ----
    bf16* Dv = g_v + ((size_t)(b * C_ + c)) * HW_;
    for (int i = tid; i < 20 * 32; i += 256) {
        int row = i >> 5, cc = (i & 31) * 4;
        int gr = r0 - 2 + row;
        if (gr < 0 || gr >= H_) continue;
        float4 o = make_float4(bvv, bvv, bvv, bvv);
#pragma unroll
        for (int dr = 0; dr < 3; dr++)
            stencil4(svi[row + dr], cc, wkv[dr * 3], wkv[dr * 3 + 1], wkv[dr * 3 + 2], o);
        *reinterpret_cast<float4*>(&sv[row][4 + cc]) = o;
        if (row >= 2 && row < 18)
            *reinterpret_cast<uint2*>(Dv + (size_t)gr * W_ + cc) = f4_to_u2(o);
    }
    __syncthreads();

    // ---- t1 = gelu(dw(v, pe1)) (18 rows incl. halo) ----
    for (int i = tid; i < 18 * 32; i += 256) {
        int row = i >> 5, cc = (i & 31) * 4;
        int gr = r0 - 1 + row;
        if (gr < 0 || gr >= H_) continue;
        float4 o = make_float4(0.f, 0.f, 0.f, 0.f);
#pragma unroll
        for (int dr = 0; dr < 3; dr++)
            stencil4(sv[row + dr], cc, w1[dr * 3], w1[dr * 3 + 1], w1[dr * 3 + 2], o);
        o.x = gelu_tanh(o.x); o.y = gelu_tanh(o.y);
        o.z = gelu_tanh(o.z); o.w = gelu_tanh(o.w);
        *reinterpret_cast<float4*>(&st1[row][4 + cc]) = o;
    }
    __syncthreads();

    // ---- pemb = dw(t1, pe2) (16 rows) -> g_pe (no hx) ----
    bf16* Dp = g_pe + ((size_t)(b * C_ + c)) * HW_;
#pragma unroll
    for (int it = 0; it < 2; it++) {
        int row = row0 + it * 8;
        float4 o = make_float4(0.f, 0.f, 0.f, 0.f);
#pragma unroll
        for (int dr = 0; dr < 3; dr++)
            stencil4(st1[row + dr], c0, w2[dr * 3], w2[dr * 3 + 1], w2[dr * 3 + 2], o);
        *reinterpret_cast<uint2*>(Dp + (size_t)(r0 + row) * W_ + c0) = f4_to_u2(o);
    }
}

// ---------------- gram via bf16 mma m16n8k16, split-K=4 ----------------------
__global__ __launch_bounds__(256) void gram_mma() {
    __shared__ float sbuf[8192];
    bf16* sqh = reinterpret_cast<bf16*>(sbuf);          // 32*136 bf16
    bf16* skh = sqh + 32 * 136;
    unsigned* squ = reinterpret_cast<unsigned*>(sqh);
    unsigned* sku = reinterpret_cast<unsigned*>(skh);
    int seg = blockIdx.x, h = blockIdx.y, b = blockIdx.z;
    const bf16* Q = g_q + ((size_t)(b * C_ + h * HD_)) * HW_;
    const bf16* K = g_k + ((size_t)(b * C_ + h * HD_)) * HW_;
    int tid = threadIdx.x, wid = tid >> 5, lane = tid & 31;
    int g = lane >> 2, tig = lane & 3;
    float acc[2][4][4] = {};
    int n0 = seg * (HW_ / GSEG);
    int klu = wid * 8;  // uint offset of this warp's 16-wide k slice
    for (int ch = 0; ch < (HW_ / GSEG) / 128; ch++) {
        int base = n0 + ch * 128;
        for (int i = tid; i < 32 * 16; i += 256) {
            int row = i >> 4, c8 = (i & 15) * 8;
            *reinterpret_cast<uint4*>(sqh + row * 136 + c8) =
                *reinterpret_cast<const uint4*>(Q + (size_t)row * HW_ + base + c8);
            *reinterpret_cast<uint4*>(skh + row * 136 + c8) =
                *reinterpret_cast<const uint4*>(K + (size_t)row * HW_ + base + c8);
        }
        __syncthreads();
        unsigned afr[2][4];
#pragma unroll
        for (int mt = 0; mt < 2; mt++) {
            int r = mt * 16 + g;
            afr[mt][0] = squ[r * 68 + klu + tig];
            afr[mt][1] = squ[(r + 8) * 68 + klu + tig];
            afr[mt][2] = squ[r * 68 + klu + 4 + tig];
            afr[mt][3] = squ[(r + 8) * 68 + klu + 4 + tig];
        }
#pragma unroll
        for (int nt = 0; nt < 4; nt++) {
            unsigned b0 = sku[(nt * 8 + g) * 68 + klu + tig];
            unsigned b1 = sku[(nt * 8 + g) * 68 + klu + 4 + tig];
#pragma unroll
            for (int mt = 0; mt < 2; mt++)
                mma_bf16(acc[mt][nt], afr[mt], b0, b1);
        }
        __syncthreads();
    }
    float* red = sbuf;
#pragma unroll
    for (int mt = 0; mt < 2; mt++)
#pragma unroll
        for (int nt = 0; nt < 4; nt++) {
            int r = mt * 16 + g, cl = nt * 8 + 2 * tig;
            red[wid * 1024 + r * 32 + cl] = acc[mt][nt][0];
            red[wid * 1024 + r * 32 + cl + 1] = acc[mt][nt][1];
            red[wid * 1024 + (r + 8) * 32 + cl] = acc[mt][nt][2];
            red[wid * 1024 + (r + 8) * 32 + cl + 1] = acc[mt][nt][3];
        }
    __syncthreads();
    float* outp = g_part + ((size_t)(b * HEADS_ + h) * GSEG + seg) * 1024;
    for (int i = tid; i < 1024; i += 256) {
        float s = 0.f;
#pragma unroll
        for (int w = 0; w < 8; w++) s += red[w * 1024 + i];
        outp[i] = s;
    }
}

// ---------------- softmax with fused q/k norm scales + temperature -----------
__global__ void softmax_kernel(const float* __restrict__ temp) {
    int bh = blockIdx.x;
    int b = bh >> 3, h = bh & 7;
    int i = threadIdx.x;
    float qs = 1.f / fmaxf(sqrtf(g_ss[b * C_ + h * HD_ + i]), 1e-12f);
    float T = __ldg(temp + h);
    float v[32];
    float mx = -1e30f;
#pragma unroll 4
    for (int j = 0; j < 32; j++) {
        float s = 0.f;
#pragma unroll
        for (int seg = 0; seg < GSEG; seg++)
            s += g_part[((size_t)bh * GSEG + seg) * 1024 + i * 32 + j];
        float ks = 1.f / fmaxf(sqrtf(g_ss[B_ * C_ + b * C_ + h * HD_ + j]), 1e-12f);
        float val = s * qs * ks * T;
        v[j] = val;
        mx = fmaxf(mx, val);
    }
    float sum = 0.f;
#pragma unroll
    for (int j = 0; j < 32; j++) {
        v[j] = expf(v[j] - mx);
        sum += v[j];
    }
    float inv = 1.f / sum;
#pragma unroll
    for (int j = 0; j < 32; j++) g_attn[bh * 1024 + i * 32 + j] = v[j] * inv;
}

// ---------------- M[b] = ao_w @ blockdiag(attn[b]) ---------------------------
__global__ void buildM_kernel(const float* __restrict__ ao_w) {
    int h = blockIdx.x, b = blockIdx.y;
    int tid = threadIdx.x;
    __shared__ float sa[32][33];
#pragma unroll
    for (int t = 0; t < 4; t++) {
        int idx = tid + t * 256;
        sa[idx >> 5][idx & 31] = g_attn[(b * HEADS_ + h) * 1024 + idx];
    }
    __syncthreads();
    float wreg[32];
#pragma unroll
    for (int c = 0; c < 32; c++) wreg[c] = ao_w[(size_t)tid * C_ + h * HD_ + c];
#pragma unroll 4
    for (int d = 0; d < 32; d++) {
        float m = 0.f;
#pragma unroll
        for (int c = 0; c < 32; c++) m += wreg[c] * sa[c][d];
        g_M[((size_t)(b * C_) + tid) * C_ + h * HD_ + d] = m;
    }
}

// ======= final GEMM: out = M[b] @ v + ao_b + pemb + hx (tf32, bf16 B) ========
__global__ __launch_bounds__(256, 2) void gemm_out_kernel(const float* __restrict__ bias,
                                                          const float* __restrict__ hx,
                                                          float* __restrict__ out) {
    extern __shared__ float sm2[];
    int b = blockIdx.z;
    int oBase = blockIdx.x * 128;
    int pBase = blockIdx.y * 128;
    int tid = threadIdx.x;
    int wid = tid >> 5, lane = tid & 31;
    int g = lane >> 2, tig = lane & 3;
    int oW = (wid >> 2) * 64;
    int pW = (wid & 3) * 32;

    const float* Mb = g_M + (size_t)b * C_ * C_;
    const bf16* Vb = g_v + (size_t)b * C_ * HW_;

    float4 aR[4];
    uint4 bR[2];
    auto ldg_stage = [&](int k0) {
#pragma unroll
        for (int i = 0; i < 4; i++) {
            int idx = tid + i * 256;
            int o = idx >> 3, kq = idx & 7;
            aR[i] = *reinterpret_cast<const float4*>(Mb + (size_t)(oBase + o) * C_ + k0 + kq * 4);
        }
#pragma unroll
        for (int i = 0; i < 2; i++) {
            int idx = tid + i * 256;
            int k = idx >> 4, c8 = (idx & 15) * 8;
            bR[i] = *reinterpret_cast<const uint4*>(Vb + (size_t)(k0 + k) * HW_ + pBase + c8);
        }
    };
    auto sts_stage = [&](int st) {
        float* sA = sm2 + st * ST_FLOATS;
        float* sB = sA + 4608;
#pragma unroll
        for (int i = 0; i < 4; i++) {
            int idx = tid + i * 256;
            int o = idx >> 3, kq = idx & 7;
            *reinterpret_cast<float4*>(sA + o * 36 + kq * 4) = aR[i];
        }
#pragma unroll
        for (int i = 0; i < 2; i++) {
            int idx = tid + i * 256;
            int k = idx >> 4, c8 = (idx & 15) * 8;
            float4 lo, hi;
            u4_to_f8(bR[i], lo, hi);
            *reinterpret_cast<float4*>(sB + k * 136 + c8) = lo;
            *reinterpret_cast<float4*>(sB + k * 136 + c8 + 4) = hi;
        }
    };

    float acc[4][4][4] = {};
    ldg_stage(0);
    for (int kc = 0; kc < 8; kc++) {
        sts_stage(kc & 1);
        __syncthreads();
        if (kc < 7) ldg_stage((kc + 1) * 32);
        unsigned* sA = reinterpret_cast<unsigned*>(sm2 + (kc & 1) * ST_FLOATS);
        unsigned* sB = sA + 4608;
#pragma unroll
        for (int s = 0; s < 32; s += 8) {
            unsigned afr[4][4];
#pragma unroll
            for (int mt = 0; mt < 4; mt++) {
                int ro = oW + mt * 16 + g;
                afr[mt][0] = sA[ro * 36 + s + tig];
                afr[mt][1] = sA[(ro + 8) * 36 + s + tig];
                afr[mt][2] = sA[ro * 36 + s + tig + 4];
                afr[mt][3] = sA[(ro + 8) * 36 + s + tig + 4];
            }
#pragma unroll
            for (int nt = 0; nt < 4; nt++) {
                int cp = pW + nt * 8 + g;
                unsigned b0 = sB[(s + tig) * 136 + cp];
                unsigned b1 = sB[(s + tig + 4) * 136 + cp];
#pragma unroll
                for (int mt = 0; mt < 4; mt++)
                    mma_tf32(acc[mt][nt], afr[mt], b0, b1);
            }
        }
        __syncthreads();
    }

    const bf16* PEb = g_pe + (size_t)b * C_ * HW_;
    const float* HXb = hx + (size_t)b * C_ * HW_;
#pragma unroll
    for (int mt = 0; mt < 4; mt++) {
        int o0 = oBase + oW + mt * 16 + g;
        int o1 = o0 + 8;
        float b0v = bias[o0], b1v = bias[o1];
#pragma unroll
        for (int nt = 0; nt < 4; nt++) {
            int p = pBase + pW + nt * 8 + 2 * tig;
            float2 h0 = *reinterpret_cast<const float2*>(HXb + (size_t)o0 * HW_ + p);
            float2 h1 = *reinterpret_cast<const float2*>(HXb + (size_t)o1 * HW_ + p);
            float2 pf0 = __bfloat1622float2(
                *reinterpret_cast<const bf162*>(PEb + (size_t)o0 * HW_ + p));
            float2 pf1 = __bfloat1622float2(
                *reinterpret_cast<const bf162*>(PEb + (size_t)o1 * HW_ + p));
            float2 r0, r1;
            r0.x = acc[mt][nt][0] + b0v + pf0.x + h0.x;
            r0.y = acc[mt][nt][1] + b0v + pf0.y + h0.y;
            r1.x = acc[mt][nt][2] + b1v + pf1.x + h1.x;
            r1.y = acc[mt][nt][3] + b1v + pf1.y + h1.y;
            *reinterpret_cast<float2*>(out + ((size_t)b * C_ + o0) * HW_ + p) = r0;
            *reinterpret_cast<float2*>(out + ((size_t)b * C_ + o1) * HW_ + p) = r1;
        }
    }
}

// -----------------------------------------------------------------------------
extern "C" void kernel_launch(void* const* d_in, const int* in_sizes, int n_in,
                              void* d_out, int out_size) {
    const float* x = (const float*)d_in[0];
    const float* hx = (const float*)d_in[1];
    const float* ln1_w = (const float*)d_in[2];
    const float* ln1_b = (const float*)d_in[3];
    const float* ln2_w = (const float*)d_in[4];
    const float* ln2_b = (const float*)d_in[5];
    const float* q_w = (const float*)d_in[6];
    const float* q_b = (const float*)d_in[7];
    const float* q_dw_w = (const float*)d_in[8];
    const float* q_dw_b = (const float*)d_in[9];
    const float* kv_w = (const float*)d_in[10];
    const float* kv_b = (const float*)d_in[11];
    const float* kv_dw_w = (const float*)d_in[12];
    const float* kv_dw_b = (const float*)d_in[13];
    const float* ao_w = (const float*)d_in[14];
    const float* ao_b = (const float*)d_in[15];
    const float* pe1_w = (const float*)d_in[16];
    const float* pe2_w = (const float*)d_in[17];
    const float* temperature = (const float*)d_in[18];
    float* out = (float*)d_out;

    float *p_Wq, *p_Wkv, *p_bq, *p_bkv, *p_rsq, *p_rskv, *p_ss;
    bf16 *p_bufA, *p_bufB, *p_q;
    cudaGetSymbolAddress((void**)&p_Wq, g_Wq);
    cudaGetSymbolAddress((void**)&p_Wkv, g_Wkv);
    cudaGetSymbolAddress((void**)&p_bq, g_bq);
    cudaGetSymbolAddress((void**)&p_bkv, g_bkv);
    cudaGetSymbolAddress((void**)&p_rsq, g_rsq);
    cudaGetSymbolAddress((void**)&p_rskv, g_rskv);
    cudaGetSymbolAddress((void**)&p_ss, g_ss);
    cudaGetSymbolAddress((void**)&p_bufA, g_bufA);
    cudaGetSymbolAddress((void**)&p_bufB, g_bufB);
    cudaGetSymbolAddress((void**)&p_q, g_q);

    const int gemm_smem = 3 * ST_FLOATS * 4;     // 107520 B (LN gemm, 3-stage)
    const int out_smem = 2 * ST_FLOATS * 4;      // 71680 B (final gemm, 2-stage)
    cudaFuncSetAttribute(gemm_ln_kernel, cudaFuncAttributeMaxDynamicSharedMemorySize, gemm_smem);
    cudaFuncSetAttribute(gemm_out_kernel, cudaFuncAttributeMaxDynamicSharedMemorySize, out_smem);

    // 1. fold LN into weights; zero sumsq accumulators
    prep_w_kernel<<<3 * C_, 256>>>(q_w, q_b, ln1_w, ln1_b, kv_w, kv_b, ln2_w, ln2_b);

    // 2. q_pre = conv1x1(ln(x)) -> bufA ; kv_pre = conv1x1(ln(hx)) -> bufB
    //    grid: o-tile fastest for L2 reuse of X
    {
        GemmArgs ga{};
        ga.X = x; ga.Wg = p_Wq; ga.bias = p_bq; ga.rsum = p_rsq;
        ga.Yh = p_bufA; ga.O = C_;
        gemm_ln_kernel<<<dim3(C_ / 128, HW_ / 128, B_), 256, gemm_smem>>>(ga);
    }
    {
        GemmArgs ga{};
        ga.X = hx; ga.Wg = p_Wkv; ga.bias = p_bkv; ga.rsum = p_rskv;
        ga.Yh = p_bufB; ga.O = 2 * C_;
        gemm_ln_kernel<<<dim3(2 * C_ / 128, HW_ / 128, B_), 256, gemm_smem>>>(ga);
    }

    // 3. q dwconv -> g_q (+sumsq)
    dwq_kernel<<<dim3(8, C_, B_), 256>>>(p_bufA, q_dw_w, q_dw_b, p_q, p_ss);

    // 4. merged kv dwconv + positional branch -> g_k, g_v, g_pe
    kvpe_kernel<<<dim3(8, C_, B_), 256>>>(kv_dw_w, kv_dw_b, pe1_w, pe2_w);

    // 5. gram (bf16 mma, split-K=4), softmax with fused norms
    gram_mma<<<dim3(GSEG, HEADS_, B_), 256>>>();
    softmax_kernel<<<B_ * HEADS_, 32>>>(temperature);

    // 6. fold attn into output projection; final fused GEMM
    buildM_kernel<<<dim3(HEADS_, B_), 256>>>(ao_w);
    gemm_out_kernel<<<dim3(C_ / 128, HW_ / 128, B_), 256, out_smem>>>(ao_b, hx, out);
}